// round 4
// baseline (speedup 1.0000x reference)
#include <cuda_runtime.h>
#include <cuda_bf16.h>

typedef unsigned int u32;

// Problem constants
#define BB 2
#define LL 2048
#define DD 1024
#define HH 16
#define MM (BB*LL)          // 4096
#define NC 32
#define CHUNK 64
#define KP 512              // packed row pitch in u32 (1024 bf16 pairs)

// ---------------- scratch (device globals, no allocation) ----------------
__device__ u32 g_Xh[MM * KP], g_Xl[MM * KP];
__device__ u32 g_Wh[4 * DD * (DD/2)], g_Wl[4 * DD * (DD/2)];
__device__ u32 g_Qh[MM * KP], g_Ql[MM * KP];
__device__ u32 g_Kh[MM * KP], g_Kl[MM * KP];
__device__ u32 g_Vh[MM * KP], g_Vl[MM * KP];
__device__ u32 g_Yh[MM * KP], g_Yl[MM * KP];
__device__ float g_S[BB * HH * NC * 64 * 64];
__device__ float g_Bm[HH * 64 * 64];

extern __shared__ unsigned char dynsmem[];

// =====================================================================
// helpers
// =====================================================================
__device__ __forceinline__ u32 smem_u32(const void* p) {
    u32 a;
    asm("{ .reg .u64 t; cvta.to.shared.u64 t, %1; cvt.u32.u64 %0, t; }"
        : "=r"(a) : "l"(p));
    return a;
}
__device__ __forceinline__ void ldsm4(u32 r[4], u32 addr) {
    asm volatile("ldmatrix.sync.aligned.m8n8.x4.shared.b16 {%0,%1,%2,%3}, [%4];"
                 : "=r"(r[0]), "=r"(r[1]), "=r"(r[2]), "=r"(r[3]) : "r"(addr));
}
__device__ __forceinline__ void mma_bf16(float c[4], const u32 a[4], u32 b0, u32 b1) {
    asm volatile(
        "mma.sync.aligned.m16n8k16.row.col.f32.bf16.bf16.f32 "
        "{%0,%1,%2,%3}, {%4,%5,%6,%7}, {%8,%9}, {%0,%1,%2,%3};"
        : "+f"(c[0]), "+f"(c[1]), "+f"(c[2]), "+f"(c[3])
        : "r"(a[0]), "r"(a[1]), "r"(a[2]), "r"(a[3]), "r"(b0), "r"(b1));
}
__device__ __forceinline__ u32 pack_hi(float v0, float v1) {
    u32 p;
    asm("cvt.rn.bf16x2.f32 %0, %1, %2;" : "=r"(p) : "f"(v1), "f"(v0));
    return p;   // low 16 = bf(v0), high 16 = bf(v1)
}
__device__ __forceinline__ void pack4(const float* v, u32& h0, u32& h1, u32& l0, u32& l1) {
    h0 = pack_hi(v[0], v[1]);
    h1 = pack_hi(v[2], v[3]);
    float r0 = v[0] - __uint_as_float(h0 << 16);
    float r1 = v[1] - __uint_as_float(h0 & 0xFFFF0000u);
    float r2 = v[2] - __uint_as_float(h1 << 16);
    float r3 = v[3] - __uint_as_float(h1 & 0xFFFF0000u);
    l0 = pack_hi(r0, r1);
    l1 = pack_hi(r2, r3);
}
__device__ __forceinline__ float4 unpack4(uint2 h, uint2 l) {
    float4 o;
    o.x = __uint_as_float(h.x << 16)         + __uint_as_float(l.x << 16);
    o.y = __uint_as_float(h.x & 0xFFFF0000u) + __uint_as_float(l.x & 0xFFFF0000u);
    o.z = __uint_as_float(h.y << 16)         + __uint_as_float(l.y << 16);
    o.w = __uint_as_float(h.y & 0xFFFF0000u) + __uint_as_float(l.y & 0xFFFF0000u);
    return o;
}

#define CP16(dst, src) \
    asm volatile("cp.async.cg.shared.global [%0], [%1], 16;" :: "r"(dst), "l"(src))
#define CPCOMMIT() asm volatile("cp.async.commit_group;")
#define CPWAIT1()  asm volatile("cp.async.wait_group 1;")

// =====================================================================
// prep: fp32 -> packed bf16 hi/lo for X and 4 weight matrices
// =====================================================================
__global__ void __launch_bounds__(256) prep_kernel(const float* __restrict__ X,
                                                   const float* __restrict__ Wq,
                                                   const float* __restrict__ Wk,
                                                   const float* __restrict__ Wv,
                                                   const float* __restrict__ Wc) {
    int idx = blockIdx.x * 256 + threadIdx.x;   // 0 .. 4194303
    const float2* src;
    u32 *dh, *dl;
    int off;
    if (idx < MM * KP) {
        src = (const float2*)X; dh = g_Xh; dl = g_Xl; off = idx;
    } else {
        int r = idx - MM * KP;
        int wi = r >> 19;
        off = r & 0x7FFFF;
        const float* w = (wi == 0) ? Wq : (wi == 1) ? Wk : (wi == 2) ? Wv : Wc;
        src = (const float2*)w;
        dh = g_Wh + ((size_t)wi << 19);
        dl = g_Wl + ((size_t)wi << 19);
    }
    float2 v = src[off];
    u32 h = pack_hi(v.x, v.y);
    float r0 = v.x - __uint_as_float(h << 16);
    float r1 = v.y - __uint_as_float(h & 0xFFFF0000u);
    dh[off] = h;
    dl[off] = pack_hi(r0, r1);
}

// =====================================================================
// Tensor-core GEMM, cp.async 3-stage, BK=64.
// SMEM per stage (64KB): Ah(16K) Al(16K) Bh(16K) Bl(16K), 128B rows,
// 16B chunks swizzled by chunk ^= (row&7).
// =====================================================================
#define GEMM_SMEM (3 * 65536)

__device__ __forceinline__ void gemm_load_stage(u32 sb,
        const u32* __restrict__ Agh, const u32* __restrict__ Agl,
        const u32* __restrict__ Bgh, const u32* __restrict__ Bgl,
        int kt, int s, int tid) {
    const int row = tid >> 1;
    const int hf = tid & 1;
    const u32 st = sb + (u32)s * 65536u;
    const size_t arow = (size_t)row * KP + kt * 32;
#pragma unroll
    for (int c4 = 0; c4 < 4; c4++) {
        const int chunk = hf * 4 + c4;
        const u32 dsto = st + (u32)(row * 128 + ((chunk ^ (row & 7)) << 4));
        const size_t so = arow + chunk * 4;
        CP16(dsto,          Agh + so);
        CP16(dsto + 16384u, Agl + so);
        CP16(dsto + 32768u, Bgh + so);
        CP16(dsto + 49152u, Bgl + so);
    }
}

template<bool PACKED>
__device__ __forceinline__ void gemm_tc_body(const u32* __restrict__ Agh,
                                             const u32* __restrict__ Agl,
                                             const u32* __restrict__ Bgh,
                                             const u32* __restrict__ Bgl,
                                             u32* __restrict__ Ch,
                                             u32* __restrict__ Cl,
                                             float* __restrict__ Cf) {
    const int tid = threadIdx.x, lane = tid & 31, wid = tid >> 5;
    const int bm = blockIdx.y * 128, bn = blockIdx.x * 128;
    const int mW = (wid >> 2) * 64, nW = (wid & 3) * 32;
    u32 sb = smem_u32(dynsmem);
    Agh += (size_t)bm * KP; Agl += (size_t)bm * KP;
    Bgh += (size_t)bn * KP; Bgl += (size_t)bn * KP;

    float acc[4][4][4];
#pragma unroll
    for (int mi = 0; mi < 4; mi++)
#pragma unroll
        for (int ni = 0; ni < 4; ni++)
#pragma unroll
            for (int r = 0; r < 4; r++) acc[mi][ni][r] = 0.f;

    gemm_load_stage(sb, Agh, Agl, Bgh, Bgl, 0, 0, tid); CPCOMMIT();
    gemm_load_stage(sb, Agh, Agl, Bgh, Bgl, 1, 1, tid); CPCOMMIT();

    for (int kt = 0; kt < 16; kt++) {
        const int s = kt % 3;
        CPWAIT1();
        __syncthreads();
        if (kt + 2 < 16)
            gemm_load_stage(sb, Agh, Agl, Bgh, Bgl, kt + 2, (kt + 2) % 3, tid);
        CPCOMMIT();

        const u32 stb = sb + (u32)s * 65536u;
#pragma unroll
        for (int ks = 0; ks < 4; ks++) {
            const int kchunk = ks * 2 + (lane >> 4);
            u32 Ah[4][4], Al[4][4];
#pragma unroll
            for (int mi = 0; mi < 4; mi++) {
                int rowA = mW + mi * 16 + (lane & 15);
                u32 ad = stb + (u32)(rowA * 128 + ((kchunk ^ (rowA & 7)) << 4));
                ldsm4(Ah[mi], ad);
                ldsm4(Al[mi], ad + 16384u);
            }
            u32 Bh0[4], Bh1[4], Bl0[4], Bl1[4];
            {
                int rowB0 = nW + (lane & 15);
                int rowB1 = rowB0 + 16;
                u32 b0 = stb + 32768u + (u32)(rowB0 * 128 + ((kchunk ^ (rowB0 & 7)) << 4));
                u32 b1 = stb + 32768u + (u32)(rowB1 * 128 + ((kchunk ^ (rowB1 & 7)) << 4));
                ldsm4(Bh0, b0); ldsm4(Bl0, b0 + 16384u);
                ldsm4(Bh1, b1); ldsm4(Bl1, b1 + 16384u);
            }
#pragma unroll
            for (int mi = 0; mi < 4; mi++) {
#pragma unroll
                for (int ni = 0; ni < 4; ni++) {
                    u32 bh0 = (ni < 2) ? Bh0[ni]     : Bh1[ni - 2];
                    u32 bh1 = (ni < 2) ? Bh0[ni + 2] : Bh1[ni];
                    u32 bl0 = (ni < 2) ? Bl0[ni]     : Bl1[ni - 2];
                    u32 bl1 = (ni < 2) ? Bl0[ni + 2] : Bl1[ni];
                    mma_bf16(acc[mi][ni], Ah[mi], bh0, bh1);
                    mma_bf16(acc[mi][ni], Ah[mi], bl0, bl1);
                    mma_bf16(acc[mi][ni], Al[mi], bh0, bh1);
                }
            }
        }
    }

    // epilogue
#pragma unroll
    for (int mi = 0; mi < 4; mi++) {
#pragma unroll
        for (int ni = 0; ni < 4; ni++) {
            int row = bm + mW + mi * 16 + (lane >> 2);
            int col = bn + nW + ni * 8 + (lane & 3) * 2;
            if (PACKED) {
                size_t pi = (size_t)row * KP + (col >> 1);
                float c0 = acc[mi][ni][0], c1 = acc[mi][ni][1];
                u32 h = pack_hi(c0, c1);
                Ch[pi] = h;
                Cl[pi] = pack_hi(c0 - __uint_as_float(h << 16),
                                 c1 - __uint_as_float(h & 0xFFFF0000u));
                size_t pi2 = pi + 8 * KP;
                float c2 = acc[mi][ni][2], c3 = acc[mi][ni][3];
                u32 h2 = pack_hi(c2, c3);
                Ch[pi2] = h2;
                Cl[pi2] = pack_hi(c2 - __uint_as_float(h2 << 16),
                                  c3 - __uint_as_float(h2 & 0xFFFF0000u));
            } else {
                *(float2*)&Cf[(size_t)row * 1024 + col] =
                    make_float2(acc[mi][ni][0], acc[mi][ni][1]);
                *(float2*)&Cf[(size_t)(row + 8) * 1024 + col] =
                    make_float2(acc[mi][ni][2], acc[mi][ni][3]);
            }
        }
    }
}

__global__ void __launch_bounds__(256) qkv_gemm_kernel() {
    const int z = blockIdx.z;
    const u32* Bh_g = g_Wh + ((size_t)z << 19);
    const u32* Bl_g = g_Wl + ((size_t)z << 19);
    u32* Ch = (z == 0) ? g_Qh : (z == 1) ? g_Kh : g_Vh;
    u32* Cl = (z == 0) ? g_Ql : (z == 1) ? g_Kl : g_Vl;
    gemm_tc_body<true>(g_Xh, g_Xl, Bh_g, Bl_g, Ch, Cl, nullptr);
}

__global__ void __launch_bounds__(256) out_gemm_kernel(float* __restrict__ out) {
    gemm_tc_body<false>(g_Yh, g_Yl, g_Wh + ((size_t)3 << 19), g_Wl + ((size_t)3 << 19),
                        nullptr, nullptr, out);
}

// =====================================================================
// Bm[h] = tril(Ltri[h]) @ tril(Ltri[h])^T
// =====================================================================
__global__ void __launch_bounds__(256) bm_kernel(const float* __restrict__ Ltri) {
    const int h = blockIdx.x;
    __shared__ float sL[64 * 64];
    const float* Lp = Ltri + (size_t)h * 4096;
#pragma unroll
    for (int p = 0; p < 4; p++) {
        int e = threadIdx.x * 4 + p * 1024;
        *(float4*)&sL[e] = *(const float4*)&Lp[e];
    }
    __syncthreads();
    for (int p = 0; p < 16; p++) {
        int idx = threadIdx.x + p * 256;
        int e = idx >> 6, d2 = idx & 63;
        int mmax = e < d2 ? e : d2;
        float s = 0.f;
        for (int m = 0; m <= mmax; m++)
            s = fmaf(sL[e * 64 + m], sL[d2 * 64 + m], s);
        g_Bm[(size_t)h * 4096 + idx] = s;
    }
}

// =====================================================================
// Phase 1: per-chunk KV state  S[i][j] = sum_t K[t][i] * V[t][j]
// =====================================================================
__global__ void __launch_bounds__(256) chunk_state_kernel() {
    const int blk = blockIdx.x;
    const int c  = blk & (NC - 1);
    const int bh = blk >> 5;
    const int b  = bh >> 4;
    const int h  = bh & 15;
    __shared__ float sK[64 * 64];
    __shared__ float sV[64 * 64];
    const size_t pbase = (size_t)(b * LL + c * CHUNK) * KP + h * 32;
    const int tid = threadIdx.x;
#pragma unroll
    for (int p = 0; p < 4; p++) {
        int e = tid * 4 + p * 1024;
        int r = e >> 6, col = e & 63;
        size_t off = pbase + (size_t)r * KP + (col >> 1);
        *(float4*)&sK[e] = unpack4(*(const uint2*)(g_Kh + off), *(const uint2*)(g_Kl + off));
        *(float4*)&sV[e] = unpack4(*(const uint2*)(g_Vh + off), *(const uint2*)(g_Vl + off));
    }
    __syncthreads();
    const int ty = tid >> 4, tx = tid & 15;
    float acc[4][4];
#pragma unroll
    for (int i = 0; i < 4; i++)
#pragma unroll
        for (int j = 0; j < 4; j++) acc[i][j] = 0.f;
    for (int t = 0; t < 64; t++) {
        float4 kv = *(const float4*)&sK[t * 64 + ty * 4];
        float4 vv = *(const float4*)&sV[t * 64 + tx * 4];
        float k[4] = {kv.x, kv.y, kv.z, kv.w};
        float v[4] = {vv.x, vv.y, vv.z, vv.w};
#pragma unroll
        for (int i = 0; i < 4; i++)
#pragma unroll
            for (int j = 0; j < 4; j++)
                acc[i][j] = fmaf(k[i], v[j], acc[i][j]);
    }
    float* Sp = g_S + ((size_t)bh * NC + c) * 4096;
#pragma unroll
    for (int i = 0; i < 4; i++) {
        float4 v = make_float4(acc[i][0], acc[i][1], acc[i][2], acc[i][3]);
        *(float4*)&Sp[(ty * 4 + i) * 64 + tx * 4] = v;
    }
}

// =====================================================================
// Phase 2: exclusive prefix over NC chunk states (parallel chains)
// =====================================================================
__global__ void __launch_bounds__(256) chunk_scan_kernel() {
    int idx = blockIdx.x * 256 + threadIdx.x;
    float* p = g_S + (size_t)(idx >> 12) * (NC * 4096) + (idx & 4095);
    float acc = 0.f;
#pragma unroll
    for (int c = 0; c < NC; c++) {
        float v = p[(size_t)c * 4096];
        p[(size_t)c * 4096] = acc;
        acc += v;
    }
}

// =====================================================================
// Phase 3: per-chunk output.
//   Y = Q @ P  +  tril(Q K^T) @ V,   then Y2 = Y @ Bm
// =====================================================================
#define P3 68

__global__ void __launch_bounds__(256) attn_chunk_kernel() {
    float* s3 = (float*)dynsmem;
    const int blk = blockIdx.x;
    const int c  = blk & (NC - 1);
    const int bh = blk >> 5;
    const int b  = bh >> 4;
    const int h  = bh & 15;

    float* sQ  = s3;
    float* sKT = s3 + 64 * P3;
    float* sAT = s3 + 2 * 64 * P3;

    const int tid = threadIdx.x;
    const int ty = tid >> 4, tx = tid & 15;
    const size_t pbase = (size_t)(b * LL + c * CHUNK) * KP + h * 32;
    const float* Pp = g_S + ((size_t)bh * NC + c) * 4096;
    const float* Bmp = g_Bm + (size_t)h * 4096;

#pragma unroll
    for (int p = 0; p < 4; p++) {
        int e = tid * 4 + p * 1024;
        int r = e >> 6, col = e & 63;
        size_t off = pbase + (size_t)r * KP + (col >> 1);
        float4 q = unpack4(*(const uint2*)(g_Qh + off), *(const uint2*)(g_Ql + off));
        *(float4*)&sQ[r * P3 + col] = q;
        float4 kv = unpack4(*(const uint2*)(g_Kh + off), *(const uint2*)(g_Kl + off));
        sKT[(col + 0) * P3 + r] = kv.x;
        sKT[(col + 1) * P3 + r] = kv.y;
        sKT[(col + 2) * P3 + r] = kv.z;
        sKT[(col + 3) * P3 + r] = kv.w;
    }
    __syncthreads();

    float acc1[4][4], acc2[4][4];
#pragma unroll
    for (int i = 0; i < 4; i++)
#pragma unroll
        for (int j = 0; j < 4; j++) { acc1[i][j] = 0.f; acc2[i][j] = 0.f; }

    for (int i = 0; i < 64; i++) {
        float q[4];
#pragma unroll
        for (int li = 0; li < 4; li++) q[li] = sQ[(ty * 4 + li) * P3 + i];
        float4 pv = __ldg((const float4*)&Pp[i * 64 + tx * 4]);
        float4 kv = *(const float4*)&sKT[i * P3 + tx * 4];
        float pr[4] = {pv.x, pv.y, pv.z, pv.w};
        float kr[4] = {kv.x, kv.y, kv.z, kv.w};
#pragma unroll
        for (int li = 0; li < 4; li++)
#pragma unroll
            for (int j = 0; j < 4; j++) {
                acc1[li][j] = fmaf(q[li], pr[j], acc1[li][j]);
                acc2[li][j] = fmaf(q[li], kr[j], acc2[li][j]);
            }
    }

#pragma unroll
    for (int li = 0; li < 4; li++)
#pragma unroll
        for (int ti = 0; ti < 4; ti++) {
            int l = ty * 4 + li, t = tx * 4 + ti;
            sAT[t * P3 + l] = (t <= l) ? acc2[li][ti] : 0.f;
        }
    __syncthreads();

#pragma unroll
    for (int p = 0; p < 4; p++) {
        int e = tid * 4 + p * 1024;
        int r = e >> 6, col = e & 63;
        size_t off = pbase + (size_t)r * KP + (col >> 1);
        *(float4*)&sKT[r * P3 + col] =
            unpack4(*(const uint2*)(g_Vh + off), *(const uint2*)(g_Vl + off));
    }
    __syncthreads();

    for (int t = 0; t < 64; t++) {
        float4 av = *(const float4*)&sAT[t * P3 + ty * 4];
        float4 vv = *(const float4*)&sKT[t * P3 + tx * 4];
        float a[4] = {av.x, av.y, av.z, av.w};
        float v[4] = {vv.x, vv.y, vv.z, vv.w};
#pragma unroll
        for (int li = 0; li < 4; li++)
#pragma unroll
            for (int j = 0; j < 4; j++)
                acc1[li][j] = fmaf(a[li], v[j], acc1[li][j]);
    }
    __syncthreads();

#pragma unroll
    for (int li = 0; li < 4; li++)
#pragma unroll
        for (int ji = 0; ji < 4; ji++)
            sQ[(tx * 4 + ji) * P3 + ty * 4 + li] = acc1[li][ji];
    __syncthreads();

    float acc3[4][4];
#pragma unroll
    for (int i = 0; i < 4; i++)
#pragma unroll
        for (int j = 0; j < 4; j++) acc3[i][j] = 0.f;
    for (int d2 = 0; d2 < 64; d2++) {
        float4 yv = *(const float4*)&sQ[d2 * P3 + ty * 4];
        float4 bm = __ldg((const float4*)&Bmp[d2 * 64 + tx * 4]);
        float y[4] = {yv.x, yv.y, yv.z, yv.w};
        float bb[4] = {bm.x, bm.y, bm.z, bm.w};
#pragma unroll
        for (int li = 0; li < 4; li++)
#pragma unroll
            for (int ei = 0; ei < 4; ei++)
                acc3[li][ei] = fmaf(y[li], bb[ei], acc3[li][ei]);
    }

#pragma unroll
    for (int li = 0; li < 4; li++) {
        int l = ty * 4 + li;
        u32 h0, h1, l0, l1;
        pack4(acc3[li], h0, h1, l0, l1);
        size_t pi = pbase + (size_t)l * KP + tx * 2;
        *(uint2*)(g_Yh + pi) = make_uint2(h0, h1);
        *(uint2*)(g_Yl + pi) = make_uint2(l0, l1);
    }
}

// =====================================================================
// kernel_launch
// =====================================================================
extern "C" void kernel_launch(void* const* d_in, const int* in_sizes, int n_in,
                              void* d_out, int out_size) {
    const float* X    = (const float*)d_in[0];
    const float* Wq   = (const float*)d_in[1];
    const float* Wk   = (const float*)d_in[2];
    const float* Wv   = (const float*)d_in[3];
    const float* Wc   = (const float*)d_in[4];
    const float* Ltri = (const float*)d_in[5];
    float* out = (float*)d_out;

    const int attn_smem = 3 * 64 * P3 * (int)sizeof(float);
    cudaFuncSetAttribute(attn_chunk_kernel,
                         cudaFuncAttributeMaxDynamicSharedMemorySize, attn_smem);
    cudaFuncSetAttribute(qkv_gemm_kernel,
                         cudaFuncAttributeMaxDynamicSharedMemorySize, GEMM_SMEM);
    cudaFuncSetAttribute(out_gemm_kernel,
                         cudaFuncAttributeMaxDynamicSharedMemorySize, GEMM_SMEM);

    prep_kernel<<<16384, 256>>>(X, Wq, Wk, Wv, Wc);

    dim3 gqkv(DD / 128, MM / 128, 3);
    qkv_gemm_kernel<<<gqkv, 256, GEMM_SMEM>>>();

    bm_kernel<<<HH, 256>>>(Ltri);
    chunk_state_kernel<<<BB * HH * NC, 256>>>();
    chunk_scan_kernel<<<512, 256>>>();
    attn_chunk_kernel<<<BB * HH * NC, 256, attn_smem>>>();

    dim3 gout(DD / 128, MM / 128, 1);
    out_gemm_kernel<<<gout, 256, GEMM_SMEM>>>(out);
}